// round 5
// baseline (speedup 1.0000x reference)
#include <cuda_runtime.h>

// Problem constants
#define BATCH   8
#define CH      64
#define GROUPS  8
#define FPG     8
#define H       256
#define Wd      256
#define PLANE   (H * Wd)        // 65536
#define TH      16              // tile height (output rows per block)
#define SROW    264             // smem row stride (floats); rows 16B-aligned
#define NTHREADS 256

// out[b,oc,h,w] = sum_{kh,kw} k[b,oc,kh,kw] * S[b,g,h+kh-1,w+kw-1]_reflect
// where S = sum of the 8 input channels in group g (kernel is broadcast over FPG).
__global__ void __launch_bounds__(NTHREADS, 4)
dynconv_kernel(const float* __restrict__ x,
               const float* __restrict__ rep,
               const float* __restrict__ Wm,
               float* __restrict__ out)
{
    // Padded group-sum tile: (TH+2) rows x 258 cols, stored at col offset +3 so
    // the interior (padded col 1..256) starts at smem index 4 -> float4 aligned.
    __shared__ __align__(16) float S[(TH + 2) * SROW];
    __shared__ float wk[8][9];

    const int tid  = threadIdx.x;
    const int g    = blockIdx.y;
    const int b    = blockIdx.z;
    const int h0   = blockIdx.x * TH;
    const int qid  = tid & 63;     // 0..63 -> column quad
    const int rsub = tid >> 6;     // 0..3  -> row phase
    const int c4   = qid * 4;

    // --- dynamic weights: k = leaky_relu(rep[b] @ W^T), rows (g*8+oc)*9+tap ---
    if (tid < 72) {
        const int oc_l = tid / 9;
        const int tap  = tid - oc_l * 9;
        const float* wrow = Wm + (size_t)(((g * 8 + oc_l) * 9) + tap) * 32;
        const float* rp   = rep + b * 32;
        float acc = 0.f;
        #pragma unroll
        for (int i = 0; i < 32; i++) acc += rp[i] * wrow[i];
        wk[oc_l][tap] = (acc > 0.f) ? acc : 0.1f * acc;
    }

    // --- load + channel-sum phase (with reflection padding) ---
    const float* xb = x + ((size_t)(b * CH + g * FPG)) * PLANE;

    for (int row = rsub; row < TH + 2; row += 4) {
        int gh = h0 + row - 1;                       // global row (pre-reflect)
        gh = (gh < 0) ? -gh : ((gh > H - 1) ? (2 * (H - 1) - gh) : gh);

        const float* rpx = xb + gh * Wd + c4;
        float a0 = 0.f, a1 = 0.f, a2 = 0.f, a3 = 0.f;
        #pragma unroll
        for (int ch = 0; ch < FPG; ch++) {
            const float4 v = *(const float4*)(rpx + (size_t)ch * PLANE);
            a0 += v.x; a1 += v.y; a2 += v.z; a3 += v.w;
        }
        *(float4*)(&S[row * SROW + 4 + c4]) = make_float4(a0, a1, a2, a3);

        if (qid == 0) {          // padded col 0  -> global col reflect(-1) = 1
            float e = 0.f;
            #pragma unroll
            for (int ch = 0; ch < FPG; ch++) e += xb[(size_t)ch * PLANE + gh * Wd + 1];
            S[row * SROW + 3] = e;
        }
        if (qid == 63) {         // padded col 257 -> global col reflect(256) = 254
            float e = 0.f;
            #pragma unroll
            for (int ch = 0; ch < FPG; ch++) e += xb[(size_t)ch * PLANE + gh * Wd + 254];
            S[row * SROW + 3 + 257] = e;
        }
    }
    __syncthreads();

    // --- compute phase: each thread does 4 consecutive cols x rows x 8 oc ---
    float* ob = out + ((size_t)(b * CH + g * FPG)) * PLANE;

    for (int r = rsub; r < TH; r += 4) {
        // S rows r..r+2 hold global rows (h0+r-1)..(h0+r+1); cols c4..c4+5 padded.
        // Middle 4 cols via aligned LDS.128, edges as scalars: 3 LDS per row.
        float s[3][6];
        #pragma unroll
        for (int i = 0; i < 3; i++) {
            const float* base = &S[(r + i) * SROW + 3 + c4];
            const float4 m = *(const float4*)(base + 1);   // 16B-aligned (idx 4+c4)
            s[i][0] = base[0];
            s[i][1] = m.x; s[i][2] = m.y; s[i][3] = m.z; s[i][4] = m.w;
            s[i][5] = base[5];
        }

        const int gh = h0 + r;
        #pragma unroll
        for (int oc = 0; oc < 8; oc++) {
            float a0 = 0.f, a1 = 0.f, a2 = 0.f, a3 = 0.f;
            #pragma unroll
            for (int i = 0; i < 3; i++) {
                #pragma unroll
                for (int k = 0; k < 3; k++) {
                    const float w = wk[oc][i * 3 + k];
                    a0 += w * s[i][k + 0];
                    a1 += w * s[i][k + 1];
                    a2 += w * s[i][k + 2];
                    a3 += w * s[i][k + 3];
                }
            }
            *(float4*)(ob + (size_t)oc * PLANE + gh * Wd + c4) =
                make_float4(a0, a1, a2, a3);
        }
    }
}

extern "C" void kernel_launch(void* const* d_in, const int* in_sizes, int n_in,
                              void* d_out, int out_size)
{
    const float* x   = (const float*)d_in[0];   // [8,64,256,256]
    const float* rep = (const float*)d_in[1];   // [8,32]
    const float* Wm  = (const float*)d_in[2];   // [576,32]
    float* out = (float*)d_out;                 // [8,64,256,256]

    dim3 grid(H / TH, GROUPS, BATCH);           // (16, 8, 8) = 1024 CTAs
    dynconv_kernel<<<grid, NTHREADS>>>(x, rep, Wm, out);
}

// round 11
// speedup vs baseline: 1.0148x; 1.0148x over previous
#include <cuda_runtime.h>

// Problem constants
#define BATCH   8
#define CH      64
#define GROUPS  8
#define FPG     8
#define H       256
#define Wd      256
#define PLANE   (H * Wd)        // 65536
#define TH      32              // tile height (output rows per block)
#define SROW    264             // smem row stride (floats); rows 16B-aligned
#define NTHREADS 256

// out[b,oc,h,w] = sum_{kh,kw} k[b,oc,kh,kw] * S[b,g,h+kh-1,w+kw-1]_reflect
// where S = sum of the 8 input channels of group g (kernel broadcast over FPG).
//
// Warp-specialized: warps 0-3 produce the padded group-sum tile S chunk by
// chunk (4 rows each); warps 4-7 consume chunks (3x3 conv x 8 oc + store),
// chasing via named barriers. Read & write DRAM streams overlap continuously.
__global__ void __launch_bounds__(NTHREADS, 2)
dynconv_kernel(const float* __restrict__ x,
               const float* __restrict__ rep,
               const float* __restrict__ Wm,
               float* __restrict__ out)
{
    // Padded tile: 34 rows (global h0-1 .. h0+32, reflected) x 258 cols.
    // Padded col pc stored at index 3+pc; interior (pc=1..256) starts at 4.
    __shared__ __align__(16) float S[(TH + 2) * SROW];
    __shared__ float wk[8][9];

    const int tid = threadIdx.x;
    const int g   = blockIdx.y;
    const int b   = blockIdx.z;
    const int h0  = blockIdx.x * TH;
    const float* xb = x + ((size_t)(b * CH + g * FPG)) * PLANE;

    if (tid < 128) {
        // ---------------- producers: warps 0..3 ----------------
        const int wid  = tid >> 5;
        const int lane = tid & 31;
        #pragma unroll 1
        for (int c = 0; c < 9; c++) {                 // chunks of 4 smem rows (last: 2)
            const int nrows = (c == 8) ? 2 : 4;
            if (wid < nrows) {
                const int srow = c * 4 + wid;
                int gh = h0 + srow - 1;               // global row (pre-reflect)
                gh = (gh < 0) ? -gh : ((gh > H - 1) ? (2 * (H - 1) - gh) : gh);
                const float* rowp = xb + (size_t)gh * Wd;

                // lane covers global cols [4*lane,4*lane+3] and [+128..]
                float4 v0[8], v1[8];
                #pragma unroll
                for (int ch = 0; ch < 8; ch++) {
                    const float* p = rowp + (size_t)ch * PLANE + 4 * lane;
                    v0[ch] = *(const float4*)(p);
                    v1[ch] = *(const float4*)(p + 128);
                }
                float4 s0 = v0[0], s1 = v1[0];
                #pragma unroll
                for (int ch = 1; ch < 8; ch++) {
                    s0.x += v0[ch].x; s0.y += v0[ch].y; s0.z += v0[ch].z; s0.w += v0[ch].w;
                    s1.x += v1[ch].x; s1.y += v1[ch].y; s1.z += v1[ch].z; s1.w += v1[ch].w;
                }
                *(float4*)&S[srow * SROW + 4 + 4 * lane]       = s0;
                *(float4*)&S[srow * SROW + 4 + 128 + 4 * lane] = s1;

                if (lane == 0) {                      // padded col 0 -> reflect(-1)=1
                    float e = 0.f;
                    #pragma unroll
                    for (int ch = 0; ch < 8; ch++) e += rowp[(size_t)ch * PLANE + 1];
                    S[srow * SROW + 3] = e;
                }
                if (lane == 31) {                     // padded col 257 -> reflect(256)=254
                    float e = 0.f;
                    #pragma unroll
                    for (int ch = 0; ch < 8; ch++) e += rowp[(size_t)ch * PLANE + 254];
                    S[srow * SROW + 3 + 257] = e;
                }
            }
            // Signal "chunks 0..c done" (program order => cumulative).
            if (c >= 1) {
                __threadfence_block();
                asm volatile("bar.arrive %0, %1;" :: "r"(c), "n"(NTHREADS) : "memory");
            }
        }
    } else {
        // ---------------- consumers: warps 4..7 ----------------
        const int ctid = tid - 128;

        // dynamic weights: k = leaky_relu(rep[b] @ W^T)
        if (ctid < 72) {
            const int oc_l = ctid / 9;
            const int tap  = ctid - oc_l * 9;
            const float* wrow = Wm + (size_t)(((g * 8 + oc_l) * 9) + tap) * 32;
            const float* rp   = rep + b * 32;
            float acc = 0.f;
            #pragma unroll
            for (int i = 0; i < 32; i++) acc += rp[i] * wrow[i];
            wk[oc_l][tap] = (acc > 0.f) ? acc : 0.1f * acc;
        }
        asm volatile("bar.sync 10, 128;" ::: "memory");   // consumer-local: wk ready

        const int qid  = ctid & 63;      // column quad
        const int rsub = ctid >> 6;      // 0 or 1
        const int c4   = qid * 4;
        float* ob = out + ((size_t)(b * CH + g * FPG)) * PLANE;

        #pragma unroll 1
        for (int j = 0; j < 8; j++) {                 // output chunks of 4 rows
            // need smem rows j*4 .. j*4+5  => producer chunks <= j+1
            asm volatile("bar.sync %0, %1;" :: "r"(j + 1), "n"(NTHREADS) : "memory");
            #pragma unroll
            for (int rr = 0; rr < 2; rr++) {
                const int r = j * 4 + rsub + rr * 2;  // output row within tile
                float s[3][6];
                #pragma unroll
                for (int i = 0; i < 3; i++) {
                    const float* base = &S[(r + i) * SROW + 3 + c4];
                    const float4 m = *(const float4*)(base + 1);  // aligned
                    s[i][0] = base[0];
                    s[i][1] = m.x; s[i][2] = m.y; s[i][3] = m.z; s[i][4] = m.w;
                    s[i][5] = base[5];
                }
                const int gh = h0 + r;
                #pragma unroll
                for (int oc = 0; oc < 8; oc++) {
                    float a0 = 0.f, a1 = 0.f, a2 = 0.f, a3 = 0.f;
                    #pragma unroll
                    for (int i = 0; i < 3; i++) {
                        #pragma unroll
                        for (int k = 0; k < 3; k++) {
                            const float w = wk[oc][i * 3 + k];
                            a0 += w * s[i][k + 0];
                            a1 += w * s[i][k + 1];
                            a2 += w * s[i][k + 2];
                            a3 += w * s[i][k + 3];
                        }
                    }
                    *(float4*)(ob + (size_t)oc * PLANE + (size_t)gh * Wd + c4) =
                        make_float4(a0, a1, a2, a3);
                }
            }
        }
    }
}

extern "C" void kernel_launch(void* const* d_in, const int* in_sizes, int n_in,
                              void* d_out, int out_size)
{
    const float* x   = (const float*)d_in[0];   // [8,64,256,256]
    const float* rep = (const float*)d_in[1];   // [8,32]
    const float* Wm  = (const float*)d_in[2];   // [576,32]
    float* out = (float*)d_out;                 // [8,64,256,256]

    dim3 grid(H / TH, GROUPS, BATCH);           // (8, 8, 8) = 512 CTAs
    dynconv_kernel<<<grid, NTHREADS>>>(x, rep, Wm, out);
}